// round 13
// baseline (speedup 1.0000x reference)
#include <cuda_runtime.h>
#include <cuda_fp16.h>
#include <cstdint>

#define NN 40000
#define NP 40064   // 313 * 128, padded row count
#define NE 320000
#define NG 64
#define IND 128
#define H4 256
#define OUTD 128
#define CAT 512
#define SFLAG (1 << 30)
#define AGG_BLKS 5008   // NP*32/256

// ---------------- scratch (device globals; no allocation allowed) ----------------
__device__ int   g_outcnt[NN];
__device__ int   g_incnt[NN];
__device__ int   g_cursor[NN];
__device__ int   g_rowptr[NN + 1];
__device__ int   g_bsum[40];
__device__ int   g_ctr;
__device__ float g_outinv[NN];
__device__ float g_ininv[NN];
__device__ int2  g_ep[NE];           // packed {src, coef_bits}, CSR-ordered by dst
__device__ float g_readout[NG * OUTD];
// fp16 activations (padded to NP rows)
__device__ __half g_xh[NP * IND];    // x as fp16
__device__ __half g_y1[NP * H4];     // layer1 GEMM out (pre-agg)
__device__ __half g_c[NP * CAT];     // concat [x1 | f1]
__device__ __half g_y2[NP * H4];     // layer2 GEMM out (pre-agg)
__device__ __half g_x2[NP * H4];     // x2
__device__ __half g_y3[NP * OUTD];   // layer3 GEMM out (pre-agg)
// weights fp16, transposed to [N][K]
// layout: W1 @0 (32768), fc1 @32768 (32768), W2 @65536 (131072), W3 @196608 (32768)
__device__ __half g_bh[229376];

// ---------------- helpers ----------------
__device__ __forceinline__ uint32_t smem_u32(const void* p) {
    uint32_t a;
    asm("{ .reg .u64 t; cvta.to.shared.u64 t, %1; cvt.u32.u64 %0, t; }" : "=r"(a) : "l"(p));
    return a;
}
__device__ __forceinline__ void cpa16(uint32_t dst, const void* src) {
    asm volatile("cp.async.cg.shared.global [%0], [%1], 16;" :: "r"(dst), "l"(src) : "memory");
}
__device__ __forceinline__ void cpa_commit() {
    asm volatile("cp.async.commit_group;" ::: "memory");
}
#define MMA16816(d, a, b)                                                     \
    asm volatile(                                                             \
        "mma.sync.aligned.m16n8k16.row.col.f32.f16.f16.f32 "                  \
        "{%0,%1,%2,%3}, {%4,%5,%6,%7}, {%8,%9}, {%0,%1,%2,%3};"               \
        : "+f"((d)[0]), "+f"((d)[1]), "+f"((d)[2]), "+f"((d)[3])              \
        : "r"((a)[0]), "r"((a)[1]), "r"((a)[2]), "r"((a)[3]),                 \
          "r"((b)[0]), "r"((b)[1]))
#define LDSM4(R, addr)                                                        \
    asm volatile("ldmatrix.sync.aligned.m8n8.x4.shared.b16 {%0,%1,%2,%3}, [%4];" \
        : "=r"((R)[0]), "=r"((R)[1]), "=r"((R)[2]), "=r"((R)[3]) : "r"(addr))

// ---------------- setup kernels ----------------
__global__ void k_zero() {
    int i = blockIdx.x * blockDim.x + threadIdx.x;
    if (i < NN) { g_outcnt[i] = 0; g_incnt[i] = 0; g_cursor[i] = 0; }
    if (i < NG * OUTD) g_readout[i] = 0.f;
    if (i < 40) g_bsum[i] = 0;
    if (i == 40) g_ctr = 0;
}

#define WTOT 229376
__global__ void k_conv(const float* __restrict__ W1, const float* __restrict__ F1,
                       const float* __restrict__ W2, const float* __restrict__ W3,
                       const float* __restrict__ x) {
    int idx = blockIdx.x * blockDim.x + threadIdx.x;
    if (idx < WTOT) {
        const float* W; int K, N, base;
        if (idx < 32768)       { W = W1; K = 128; N = 256; base = 0; }
        else if (idx < 65536)  { W = F1; K = 128; N = 256; base = 32768; }
        else if (idx < 196608) { W = W2; K = 512; N = 256; base = 65536; }
        else                   { W = W3; K = 256; N = 128; base = 196608; }
        int li = idx - base;
        int k = li % K, n = li / K;
        g_bh[idx] = __float2half_rn(W[k * N + n]);
    } else {
        int j = idx - WTOT;
        if (j < NP * IND) {
            float v = (j < NN * IND) ? x[j] : 0.f;
            g_xh[j] = __float2half_rn(v);
        }
    }
}

__global__ void k_deg(const int* __restrict__ src, const int* __restrict__ dst) {
    int e = blockIdx.x * blockDim.x + threadIdx.x;
    if (e < NE) {
        atomicAdd(&g_outcnt[src[e]], 1);
        atomicAdd(&g_incnt[dst[e]], 1);
    }
}

// fused scan: per-block scan + single-word atomic publish + parallel lookback
__global__ void k_scan() {
    __shared__ int sh[1024];
    __shared__ int pvals[40];
    __shared__ int pre;
    int b = blockIdx.x, t = threadIdx.x;
    int idx = b * 1024 + t;
    int v = (idx < NN) ? g_incnt[idx] : 0;
    if (idx < NN) {
        g_ininv[idx]  = rsqrtf((float)max(v, 1));
        g_outinv[idx] = rsqrtf((float)max(g_outcnt[idx], 1));
    }
    sh[t] = v;
    __syncthreads();
#pragma unroll
    for (int off = 1; off < 1024; off <<= 1) {
        int u = (t >= off) ? sh[t - off] : 0;
        __syncthreads();
        sh[t] += u;
        __syncthreads();
    }
    int incl = sh[t];
    if (t == 1023) atomicExch(&g_bsum[b], incl | SFLAG);
    if (t < b) {
        int a;
        do { a = atomicAdd(&g_bsum[t], 0); } while (!(a & SFLAG));
        pvals[t] = a & ~SFLAG;
    }
    __syncthreads();
    if (t == 0) {
        int s = 0;
        for (int i = 0; i < b; i++) s += pvals[i];
        pre = s;
    }
    __syncthreads();
    if (idx <= NN) g_rowptr[idx] = incl - v + pre;
}

__global__ void k_place(const int* __restrict__ src, const int* __restrict__ dst,
                        const float* __restrict__ w) {
    int e = blockIdx.x * blockDim.x + threadIdx.x;
    if (e >= NE) return;
    float4 ww = *(const float4*)(w + 4 * e);
    float m = fmaxf(fmaxf(ww.x, ww.y), fmaxf(ww.z, ww.w));
    int d = dst[e];
    int s = src[e];
    int pos = g_rowptr[d] + atomicAdd(&g_cursor[d], 1);
    g_ep[pos] = make_int2(s, __float_as_int(m * g_outinv[s]));
}

// ---------------- 128-d half-aggregation: one warp per dst node ----------------
// relu + fp16 out; input rows stride ldI with column offset iOff, output likewise.
__global__ void k_agg(const __half* __restrict__ in, int ldI, int iOff,
                      __half* __restrict__ oh, int ldO, int oOff) {
    int warp = (blockIdx.x * blockDim.x + threadIdx.x) >> 5;
    int lane = threadIdx.x & 31;
    if (warp >= NP) return;
    if (warp >= NN) {
        uint2 z = {};
        ((uint2*)(oh + (size_t)warp * ldO + oOff))[lane] = z;
        return;
    }
    int beg = g_rowptr[warp];
    int end = g_rowptr[warp + 1];
    float2 acc[2];
    acc[0] = make_float2(0.f, 0.f);
    acc[1] = make_float2(0.f, 0.f);
    int e = beg;
    for (; e + 3 < end; e += 4) {
        int2 p0 = g_ep[e], p1 = g_ep[e + 1], p2 = g_ep[e + 2], p3 = g_ep[e + 3];
        uint2 t0 = ((const uint2*)(in + (size_t)p0.x * ldI + iOff))[lane];
        uint2 t1 = ((const uint2*)(in + (size_t)p1.x * ldI + iOff))[lane];
        uint2 t2 = ((const uint2*)(in + (size_t)p2.x * ldI + iOff))[lane];
        uint2 t3 = ((const uint2*)(in + (size_t)p3.x * ldI + iOff))[lane];
        float c0 = __int_as_float(p0.y), c1 = __int_as_float(p1.y);
        float c2 = __int_as_float(p2.y), c3 = __int_as_float(p3.y);
        const uint32_t* w0 = (const uint32_t*)&t0;
        const uint32_t* w1 = (const uint32_t*)&t1;
        const uint32_t* w2 = (const uint32_t*)&t2;
        const uint32_t* w3 = (const uint32_t*)&t3;
#pragma unroll
        for (int v = 0; v < 2; v++) {
            float2 f0 = __half22float2(*(const __half2*)&w0[v]);
            float2 f1 = __half22float2(*(const __half2*)&w1[v]);
            float2 f2 = __half22float2(*(const __half2*)&w2[v]);
            float2 f3 = __half22float2(*(const __half2*)&w3[v]);
            acc[v].x = fmaf(c0, f0.x, fmaf(c1, f1.x, fmaf(c2, f2.x, fmaf(c3, f3.x, acc[v].x))));
            acc[v].y = fmaf(c0, f0.y, fmaf(c1, f1.y, fmaf(c2, f2.y, fmaf(c3, f3.y, acc[v].y))));
        }
    }
    for (; e < end; e++) {
        int2 p = g_ep[e];
        float c = __int_as_float(p.y);
        uint2 t = ((const uint2*)(in + (size_t)p.x * ldI + iOff))[lane];
        const uint32_t* w = (const uint32_t*)&t;
#pragma unroll
        for (int v = 0; v < 2; v++) {
            float2 f = __half22float2(*(const __half2*)&w[v]);
            acc[v].x = fmaf(c, f.x, acc[v].x);
            acc[v].y = fmaf(c, f.y, acc[v].y);
        }
    }
    float inv = g_ininv[warp];
    uint2 ov;
    uint32_t* ow = (uint32_t*)&ov;
#pragma unroll
    for (int v = 0; v < 2; v++) {
        __half2 a = __floats2half2_rn(fmaxf(acc[v].x * inv, 0.f), fmaxf(acc[v].y * inv, 0.f));
        ow[v] = *(uint32_t*)&a;
    }
    ((uint2*)(oh + (size_t)warp * ldO + oOff))[lane] = ov;
}

// ---------------- agg3: gather y3 (128-d), relu, readout atomics + fused L2-norm ----------------
__global__ void k_agg3(const __half* __restrict__ in, const int* __restrict__ gid,
                       float* __restrict__ out) {
    int warp = (blockIdx.x * blockDim.x + threadIdx.x) >> 5;
    int lane = threadIdx.x & 31;
    if (warp < NN) {
        int beg = g_rowptr[warp];
        int end = g_rowptr[warp + 1];
        float2 acc[2];
        acc[0] = make_float2(0.f, 0.f);
        acc[1] = make_float2(0.f, 0.f);
        int e = beg;
        for (; e + 3 < end; e += 4) {
            int2 p0 = g_ep[e], p1 = g_ep[e + 1], p2 = g_ep[e + 2], p3 = g_ep[e + 3];
            uint2 t0 = ((const uint2*)(in + (size_t)p0.x * OUTD))[lane];
            uint2 t1 = ((const uint2*)(in + (size_t)p1.x * OUTD))[lane];
            uint2 t2 = ((const uint2*)(in + (size_t)p2.x * OUTD))[lane];
            uint2 t3 = ((const uint2*)(in + (size_t)p3.x * OUTD))[lane];
            float c0 = __int_as_float(p0.y), c1 = __int_as_float(p1.y);
            float c2 = __int_as_float(p2.y), c3 = __int_as_float(p3.y);
            const uint32_t* w0 = (const uint32_t*)&t0;
            const uint32_t* w1 = (const uint32_t*)&t1;
            const uint32_t* w2 = (const uint32_t*)&t2;
            const uint32_t* w3 = (const uint32_t*)&t3;
#pragma unroll
            for (int v = 0; v < 2; v++) {
                float2 f0 = __half22float2(*(const __half2*)&w0[v]);
                float2 f1 = __half22float2(*(const __half2*)&w1[v]);
                float2 f2 = __half22float2(*(const __half2*)&w2[v]);
                float2 f3 = __half22float2(*(const __half2*)&w3[v]);
                acc[v].x = fmaf(c0, f0.x, fmaf(c1, f1.x, fmaf(c2, f2.x, fmaf(c3, f3.x, acc[v].x))));
                acc[v].y = fmaf(c0, f0.y, fmaf(c1, f1.y, fmaf(c2, f2.y, fmaf(c3, f3.y, acc[v].y))));
            }
        }
        for (; e < end; e++) {
            int2 p = g_ep[e];
            float c = __int_as_float(p.y);
            uint2 t = ((const uint2*)(in + (size_t)p.x * OUTD))[lane];
            const uint32_t* w = (const uint32_t*)&t;
#pragma unroll
            for (int v = 0; v < 2; v++) {
                float2 f = __half22float2(*(const __half2*)&w[v]);
                acc[v].x = fmaf(c, f.x, acc[v].x);
                acc[v].y = fmaf(c, f.y, acc[v].y);
            }
        }
        float inv = g_ininv[warp];
        int g = gid[warp];
        float* r = g_readout + g * OUTD + lane * 4;
        atomicAdd(r + 0, fmaxf(acc[0].x * inv, 0.f));
        atomicAdd(r + 1, fmaxf(acc[0].y * inv, 0.f));
        atomicAdd(r + 2, fmaxf(acc[1].x * inv, 0.f));
        atomicAdd(r + 3, fmaxf(acc[1].y * inv, 0.f));
    }
    // last-block does the final L2 normalization
    __syncthreads();
    __threadfence();
    __shared__ int isLast;
    if (threadIdx.x == 0)
        isLast = (atomicAdd(&g_ctr, 1) == AGG_BLKS - 1);
    __syncthreads();
    if (!isLast) return;
    int wid = threadIdx.x >> 5;
    for (int g = wid; g < NG; g += 8) {
        float v[4];
        float ss = 0.f;
#pragma unroll
        for (int i = 0; i < 4; i++) {
            v[i] = __ldcg(&g_readout[g * OUTD + lane * 4 + i]);
            ss += v[i] * v[i];
        }
#pragma unroll
        for (int o = 16; o > 0; o >>= 1) ss += __shfl_xor_sync(0xffffffffu, ss, o);
        float nrm = fmaxf(sqrtf(ss), 1e-12f);
#pragma unroll
        for (int i = 0; i < 4; i++) out[g * OUTD + lane * 4 + i] = v[i] / nrm;
    }
}

// ---------------- fp16 single-pass mma.sync GEMM, 3-stage pipeline ----------------
// Block tile 128x128, BK=32/stage, 3 stages, one sync per chunk. 80B-padded smem rows.
template <int K>
__global__ __launch_bounds__(256, 2) void k_mma(
    const __half* __restrict__ Ah, const __half* __restrict__ Bh,
    __half* __restrict__ Ch, int ldC, int colOff) {
    extern __shared__ __align__(16) uint8_t smem[];
    constexpr int NC = K / 32;
    constexpr uint32_t AH_ = 0, BH_ = 10240, STG = 20480;
    const int tid = threadIdx.x;
    const int wid = tid >> 5, lane = tid & 31;
    const int wm = wid & 3, wn = wid >> 2;
    const int m0 = blockIdx.x * 128;
    const uint32_t sb = smem_u32(smem);

    float acc[2][8][4];
#pragma unroll
    for (int mi = 0; mi < 2; mi++)
#pragma unroll
        for (int ni = 0; ni < 8; ni++)
#pragma unroll
            for (int r = 0; r < 4; r++) acc[mi][ni][r] = 0.f;

    const int lrow = tid & 127;
    const bool isB = tid >= 128;
    const __half* gS = isB ? (Bh + (size_t)lrow * K)
                           : (Ah + (size_t)(m0 + lrow) * K);
    const uint32_t gD = (isB ? BH_ : AH_) + (uint32_t)lrow * 80;

    const uint32_t aoff = AH_ + (uint32_t)(wm * 32 + (lane & 7) + ((lane >> 3) & 1) * 8) * 80 +
                          (lane >> 4) * 16;
    const uint32_t boff = BH_ + (uint32_t)(wn * 64 + ((lane >> 4) & 1) * 8 + (lane & 7)) * 80 +
                          ((lane >> 3) & 1) * 16;

    {
        uint32_t st = sb;
        const __half* gp = gS;
#pragma unroll
        for (int j = 0; j < 4; j++) cpa16(st + gD + j * 16, gp + j * 8);
        cpa_commit();
        st = sb + STG;
        gp = gS + 32;
#pragma unroll
        for (int j = 0; j < 4; j++) cpa16(st + gD + j * 16, gp + j * 8);
        cpa_commit();
    }

    for (int c = 0; c < NC; c++) {
        if (c + 1 < NC)
            asm volatile("cp.async.wait_group 1;" ::: "memory");
        else
            asm volatile("cp.async.wait_group 0;" ::: "memory");
        __syncthreads();
        if (c + 2 < NC) {
            uint32_t st = sb + ((c + 2) % 3) * STG;
            const __half* gp = gS + (c + 2) * 32;
#pragma unroll
            for (int j = 0; j < 4; j++) cpa16(st + gD + j * 16, gp + j * 8);
            cpa_commit();
        }
        uint32_t st = sb + (c % 3) * STG;
#pragma unroll
        for (int kk = 0; kk < 2; kk++) {
            const uint32_t ko = kk * 32;
            uint32_t af[2][4], bf[8][2];
#pragma unroll
            for (int mi = 0; mi < 2; mi++) LDSM4(af[mi], st + aoff + mi * 1280 + ko);
#pragma unroll
            for (int p = 0; p < 4; p++) {
                uint32_t r4[4];
                LDSM4(r4, st + boff + p * 1280 + ko);
                bf[2 * p][0] = r4[0]; bf[2 * p][1] = r4[1];
                bf[2 * p + 1][0] = r4[2]; bf[2 * p + 1][1] = r4[3];
            }
#pragma unroll
            for (int mi = 0; mi < 2; mi++)
#pragma unroll
                for (int ni = 0; ni < 8; ni++) MMA16816(acc[mi][ni], af[mi], bf[ni]);
        }
    }

    const int g = lane >> 2, q = lane & 3;
#pragma unroll
    for (int mi = 0; mi < 2; mi++)
#pragma unroll
        for (int ni = 0; ni < 8; ni++) {
            int r0 = m0 + wm * 32 + mi * 16 + g;
            int cc = colOff + wn * 64 + ni * 8 + 2 * q;
            __half2 a = __floats2half2_rn(acc[mi][ni][0], acc[mi][ni][1]);
            __half2 b = __floats2half2_rn(acc[mi][ni][2], acc[mi][ni][3]);
            *(__half2*)(Ch + (size_t)r0 * ldC + cc) = a;
            *(__half2*)(Ch + (size_t)(r0 + 8) * ldC + cc) = b;
        }
}

// ---------------- fc1 GEMM (K=128, full N=256 per CTA) + fused LayerNorm + ReLU ----------------
__global__ __launch_bounds__(256, 2) void k_mma_fc1(
    const __half* __restrict__ Ah, const __half* __restrict__ Bh,
    __half* __restrict__ Ch,
    const float* __restrict__ gamma, const float* __restrict__ beta) {
    extern __shared__ __align__(16) uint8_t smem[];
    constexpr int NC = 4;  // K=128 / 32
    constexpr uint32_t AH_ = 0, BH_ = 5120, STG = 25600;
    const int tid = threadIdx.x;
    const int wid = tid >> 5, lane = tid & 31;
    const int wm = wid & 1, wn = wid >> 1;  // 2 x 4
    const int m0 = blockIdx.x * 64;
    const uint32_t sb = smem_u32(smem);

    float acc[2][8][4];
#pragma unroll
    for (int mi = 0; mi < 2; mi++)
#pragma unroll
        for (int ni = 0; ni < 8; ni++)
#pragma unroll
            for (int r = 0; r < 4; r++) acc[mi][ni][r] = 0.f;

    const __half* bSrc = Bh + (size_t)tid * 128;
    const uint32_t bDst = BH_ + (uint32_t)tid * 80;
    const __half* aSrc = Ah + (size_t)(m0 + tid) * 128;
    const uint32_t aDst = AH_ + (uint32_t)tid * 80;
    const bool isA = tid < 64;

    const uint32_t aoff = AH_ + (uint32_t)(wm * 32 + (lane & 7) + ((lane >> 3) & 1) * 8) * 80 +
                          (lane >> 4) * 16;
    const uint32_t boff = BH_ + (uint32_t)(wn * 64 + ((lane >> 4) & 1) * 8 + (lane & 7)) * 80 +
                          ((lane >> 3) & 1) * 16;

#pragma unroll
    for (int s = 0; s < 2; s++) {
        uint32_t st = sb + s * STG;
#pragma unroll
        for (int j = 0; j < 4; j++) cpa16(st + bDst + j * 16, bSrc + s * 32 + j * 8);
        if (isA)
#pragma unroll
            for (int j = 0; j < 4; j++) cpa16(st + aDst + j * 16, aSrc + s * 32 + j * 8);
        cpa_commit();
    }

    for (int c = 0; c < NC; c++) {
        if (c + 1 < NC)
            asm volatile("cp.async.wait_group 1;" ::: "memory");
        else
            asm volatile("cp.async.wait_group 0;" ::: "memory");
        __syncthreads();
        if (c + 2 < NC) {
            uint32_t st = sb + ((c + 2) % 3) * STG;
#pragma unroll
            for (int j = 0; j < 4; j++) cpa16(st + bDst + j * 16, bSrc + (c + 2) * 32 + j * 8);
            if (isA)
#pragma unroll
                for (int j = 0; j < 4; j++) cpa16(st + aDst + j * 16, aSrc + (c + 2) * 32 + j * 8);
            cpa_commit();
        }
        uint32_t st = sb + (c % 3) * STG;
#pragma unroll
        for (int kk = 0; kk < 2; kk++) {
            const uint32_t ko = kk * 32;
            uint32_t af[2][4], bf[8][2];
#pragma unroll
            for (int mi = 0; mi < 2; mi++) LDSM4(af[mi], st + aoff + mi * 1280 + ko);
#pragma unroll
            for (int p = 0; p < 4; p++) {
                uint32_t r4[4];
                LDSM4(r4, st + boff + p * 1280 + ko);
                bf[2 * p][0] = r4[0]; bf[2 * p][1] = r4[1];
                bf[2 * p + 1][0] = r4[2]; bf[2 * p + 1][1] = r4[3];
            }
#pragma unroll
            for (int mi = 0; mi < 2; mi++)
#pragma unroll
                for (int ni = 0; ni < 8; ni++) MMA16816(acc[mi][ni], af[mi], bf[ni]);
        }
    }

    // ---- fused LayerNorm over 256 cols ----
    __syncthreads();
    float2* part = (float2*)smem;  // [64 rows][4 wn]
    const int g = lane >> 2, q = lane & 3;
#pragma unroll
    for (int mi = 0; mi < 2; mi++) {
        float s0 = 0.f, ss0 = 0.f, s8 = 0.f, ss8 = 0.f;
#pragma unroll
        for (int ni = 0; ni < 8; ni++) {
            float v0 = acc[mi][ni][0], v1 = acc[mi][ni][1];
            float v2 = acc[mi][ni][2], v3 = acc[mi][ni][3];
            s0 += v0 + v1; ss0 += v0 * v0 + v1 * v1;
            s8 += v2 + v3; ss8 += v2 * v2 + v3 * v3;
        }
#pragma unroll
        for (int o = 1; o < 4; o <<= 1) {
            s0 += __shfl_xor_sync(0xffffffffu, s0, o);
            ss0 += __shfl_xor_sync(0xffffffffu, ss0, o);
            s8 += __shfl_xor_sync(0xffffffffu, s8, o);
            ss8 += __shfl_xor_sync(0xffffffffu, ss8, o);
        }
        if (q == 0) {
            int lr = wm * 32 + mi * 16 + g;
            part[lr * 4 + wn] = make_float2(s0, ss0);
            part[(lr + 8) * 4 + wn] = make_float2(s8, ss8);
        }
    }
    __syncthreads();
#pragma unroll
    for (int mi = 0; mi < 2; mi++) {
        int lr = wm * 32 + mi * 16 + g;
        float2 a0 = part[lr * 4 + 0], a1 = part[lr * 4 + 1];
        float2 a2 = part[lr * 4 + 2], a3 = part[lr * 4 + 3];
        float s = a0.x + a1.x + a2.x + a3.x;
        float ss = a0.y + a1.y + a2.y + a3.y;
        float mean0 = s * (1.f / 256.f);
        float rstd0 = rsqrtf(ss * (1.f / 256.f) - mean0 * mean0 + 1e-5f);
        a0 = part[(lr + 8) * 4 + 0]; a1 = part[(lr + 8) * 4 + 1];
        a2 = part[(lr + 8) * 4 + 2]; a3 = part[(lr + 8) * 4 + 3];
        s = a0.x + a1.x + a2.x + a3.x;
        ss = a0.y + a1.y + a2.y + a3.y;
        float mean8 = s * (1.f / 256.f);
        float rstd8 = rsqrtf(ss * (1.f / 256.f) - mean8 * mean8 + 1e-5f);
        int r0 = m0 + lr;
#pragma unroll
        for (int ni = 0; ni < 8; ni++) {
            int col = wn * 64 + ni * 8 + 2 * q;
            float2 gg = *(const float2*)(gamma + col);
            float2 bb = *(const float2*)(beta + col);
            float v0 = fmaxf((acc[mi][ni][0] - mean0) * rstd0 * gg.x + bb.x, 0.f);
            float v1 = fmaxf((acc[mi][ni][1] - mean0) * rstd0 * gg.y + bb.y, 0.f);
            float v2 = fmaxf((acc[mi][ni][2] - mean8) * rstd8 * gg.x + bb.x, 0.f);
            float v3 = fmaxf((acc[mi][ni][3] - mean8) * rstd8 * gg.y + bb.y, 0.f);
            __half2 h0 = __floats2half2_rn(v0, v1);
            __half2 h1 = __floats2half2_rn(v2, v3);
            *(__half2*)(Ch + (size_t)r0 * CAT + H4 + col) = h0;
            *(__half2*)(Ch + (size_t)(r0 + 8) * CAT + H4 + col) = h1;
        }
    }
}

// ---------------- launch ----------------
extern "C" void kernel_launch(void* const* d_in, const int* in_sizes, int n_in,
                              void* d_out, int out_size) {
    const float* x    = (const float*)d_in[0];
    const float* w    = (const float*)d_in[1];
    const float* W1   = (const float*)d_in[2];
    const float* fc1W = (const float*)d_in[3];
    const float* gam  = (const float*)d_in[4];
    const float* bet  = (const float*)d_in[5];
    const float* W2   = (const float*)d_in[6];
    const float* W3   = (const float*)d_in[7];
    const int*   src  = (const int*)d_in[8];
    const int*   dst  = (const int*)d_in[9];
    const int*   gid  = (const int*)d_in[10];
    float* out = (float*)d_out;

    __half *p_bh, *p_xh, *p_y1, *p_c, *p_y2, *p_x2, *p_y3;
    cudaGetSymbolAddress((void**)&p_bh, g_bh);
    cudaGetSymbolAddress((void**)&p_xh, g_xh);
    cudaGetSymbolAddress((void**)&p_y1, g_y1);
    cudaGetSymbolAddress((void**)&p_c, g_c);
    cudaGetSymbolAddress((void**)&p_y2, g_y2);
    cudaGetSymbolAddress((void**)&p_x2, g_x2);
    cudaGetSymbolAddress((void**)&p_y3, g_y3);

    const int SMEM = 61440;
    const int SMEM_FC1 = 76800;
    cudaFuncSetAttribute(k_mma<128>, cudaFuncAttributeMaxDynamicSharedMemorySize, SMEM);
    cudaFuncSetAttribute(k_mma<512>, cudaFuncAttributeMaxDynamicSharedMemorySize, SMEM);
    cudaFuncSetAttribute(k_mma<256>, cudaFuncAttributeMaxDynamicSharedMemorySize, SMEM);
    cudaFuncSetAttribute(k_mma_fc1, cudaFuncAttributeMaxDynamicSharedMemorySize, SMEM_FC1);

    // side streams + events (created once, on first — non-capture — call)
    static cudaStream_t s1 = nullptr, s2 = nullptr;
    static cudaEvent_t ev0 = nullptr, ev_conv = nullptr, ev_g1h0 = nullptr, ev_g1h1 = nullptr,
                       ev_fc1 = nullptr, ev_y2h0 = nullptr, ev_x2h0 = nullptr;
    if (s1 == nullptr) {
        cudaStreamCreateWithFlags(&s1, cudaStreamNonBlocking);
        cudaStreamCreateWithFlags(&s2, cudaStreamNonBlocking);
        cudaEventCreateWithFlags(&ev0, cudaEventDisableTiming);
        cudaEventCreateWithFlags(&ev_conv, cudaEventDisableTiming);
        cudaEventCreateWithFlags(&ev_g1h0, cudaEventDisableTiming);
        cudaEventCreateWithFlags(&ev_g1h1, cudaEventDisableTiming);
        cudaEventCreateWithFlags(&ev_fc1, cudaEventDisableTiming);
        cudaEventCreateWithFlags(&ev_y2h0, cudaEventDisableTiming);
        cudaEventCreateWithFlags(&ev_x2h0, cudaEventDisableTiming);
    }

    const int TB = 256;
    const int GX = NP / 128;   // 313
    const int GX64 = NP / 64;  // 626

    // ---- fork: side stream 1 = conversion + layer-1 GEMM halves (graph-independent)
    cudaEventRecord(ev0, 0);
    cudaStreamWaitEvent(s1, ev0, 0);
    k_conv<<<(WTOT + NP * IND + TB - 1) / TB, TB, 0, s1>>>(W1, fc1W, W2, W3, x);
    cudaEventRecord(ev_conv, s1);
    k_mma<128><<<GX, TB, SMEM, s1>>>(p_xh, p_bh + 0, p_y1, H4, 0);
    cudaEventRecord(ev_g1h0, s1);
    k_mma<128><<<GX, TB, SMEM, s1>>>(p_xh, p_bh + 128 * 128, p_y1, H4, 128);
    cudaEventRecord(ev_g1h1, s1);
    // side stream 2: fc1 GEMM + fused LN (needs conv output only)
    cudaStreamWaitEvent(s2, ev_conv, 0);
    k_mma_fc1<<<GX64, TB, SMEM_FC1, s2>>>(p_xh, p_bh + 32768, p_c, gam, bet);
    cudaEventRecord(ev_fc1, s2);

    // main chain: CSR build
    k_zero<<<(NN + TB - 1) / TB, TB>>>();
    k_deg<<<(NE + TB - 1) / TB, TB>>>(src, dst);
    k_scan<<<40, 1024>>>();
    k_place<<<(NE + TB - 1) / TB, TB>>>(src, dst, w);

    // layer 1 aggregation in halves (each waits only on its y1 half)
    cudaStreamWaitEvent(0, ev_g1h0, 0);
    k_agg<<<AGG_BLKS, TB>>>(p_y1, H4, 0, p_c, CAT, 0);
    cudaStreamWaitEvent(0, ev_g1h1, 0);
    k_agg<<<AGG_BLKS, TB>>>(p_y1, H4, 128, p_c, CAT, 128);
    cudaStreamWaitEvent(0, ev_fc1, 0);  // concat now complete

    // layer 2 pipelined: gemm_h0 -> [agg_h0 on s1 || gemm_h1 on main] -> agg_h1
    k_mma<512><<<GX, TB, SMEM>>>(p_c, p_bh + 65536, p_y2, H4, 0);
    cudaEventRecord(ev_y2h0, 0);
    cudaStreamWaitEvent(s1, ev_y2h0, 0);
    k_agg<<<AGG_BLKS, TB, 0, s1>>>(p_y2, H4, 0, p_x2, H4, 0);
    cudaEventRecord(ev_x2h0, s1);
    k_mma<512><<<GX, TB, SMEM>>>(p_c, p_bh + 65536 + 128 * 512, p_y2, H4, 128);
    k_agg<<<AGG_BLKS, TB>>>(p_y2, H4, 128, p_x2, H4, 128);
    cudaStreamWaitEvent(0, ev_x2h0, 0);

    // layer 3: GEMM 256->128, then agg + readout + fused normalize
    k_mma<256><<<GX, TB, SMEM>>>(p_x2, p_bh + 196608, p_y3, OUTD, 0);
    k_agg3<<<AGG_BLKS, TB>>>(p_y3, gid, out);
}

// round 14
// speedup vs baseline: 1.1846x; 1.1846x over previous
#include <cuda_runtime.h>
#include <cuda_fp16.h>
#include <cstdint>

#define NN 40000
#define NP 40064   // 313 * 128, padded row count
#define NE 320000
#define NG 64
#define IND 128
#define H4 256
#define OUTD 128
#define CAT 512
#define SFLAG (1 << 30)

// ---------------- scratch (device globals; no allocation allowed) ----------------
__device__ int   g_outcnt[NN];
__device__ int   g_incnt[NN];
__device__ int   g_cursor[NN];
__device__ int   g_rowptr[NN + 1];
__device__ int   g_bsum[40];
__device__ float g_outinv[NN];
__device__ float g_ininv[NN];
__device__ int2  g_ep[NE];           // packed {src, coef_bits}, CSR-ordered by dst
__device__ float g_readout[NG * OUTD];
// fp16 activations (padded to NP rows)
__device__ __half g_xh[NP * IND];    // x as fp16
__device__ __half g_y1[NP * H4];     // layer1 GEMM out (pre-agg)
__device__ __half g_f1h[NP * H4];    // fc1 raw out (pre-LN)
__device__ __half g_c[NP * CAT];     // concat [x1 | f1]
__device__ __half g_y2[NP * H4];     // layer2 GEMM out (pre-agg)
__device__ __half g_x2[NP * H4];     // x2
__device__ __half g_y3[NP * OUTD];   // layer3 GEMM out (pre-agg)
// weights fp16, transposed to [N][K]
// layout: W1 @0 (32768), fc1 @32768 (32768), W2 @65536 (131072), W3 @196608 (32768)
__device__ __half g_bh[229376];

// ---------------- helpers ----------------
template <int V> struct VecSel;
template <> struct VecSel<2> { using T = uint2; };
template <> struct VecSel<4> { using T = uint4; };

__device__ __forceinline__ uint32_t smem_u32(const void* p) {
    uint32_t a;
    asm("{ .reg .u64 t; cvta.to.shared.u64 t, %1; cvt.u32.u64 %0, t; }" : "=r"(a) : "l"(p));
    return a;
}
__device__ __forceinline__ void cpa16(uint32_t dst, const void* src) {
    asm volatile("cp.async.cg.shared.global [%0], [%1], 16;" :: "r"(dst), "l"(src) : "memory");
}
__device__ __forceinline__ void cpa_commit() {
    asm volatile("cp.async.commit_group;" ::: "memory");
}
#define MMA16816(d, a, b)                                                     \
    asm volatile(                                                             \
        "mma.sync.aligned.m16n8k16.row.col.f32.f16.f16.f32 "                  \
        "{%0,%1,%2,%3}, {%4,%5,%6,%7}, {%8,%9}, {%0,%1,%2,%3};"               \
        : "+f"((d)[0]), "+f"((d)[1]), "+f"((d)[2]), "+f"((d)[3])              \
        : "r"((a)[0]), "r"((a)[1]), "r"((a)[2]), "r"((a)[3]),                 \
          "r"((b)[0]), "r"((b)[1]))
#define LDSM4(R, addr)                                                        \
    asm volatile("ldmatrix.sync.aligned.m8n8.x4.shared.b16 {%0,%1,%2,%3}, [%4];" \
        : "=r"((R)[0]), "=r"((R)[1]), "=r"((R)[2]), "=r"((R)[3]) : "r"(addr))

// ---------------- setup kernels ----------------
__global__ void k_zero() {
    int i = blockIdx.x * blockDim.x + threadIdx.x;
    if (i < NN) { g_outcnt[i] = 0; g_incnt[i] = 0; g_cursor[i] = 0; }
    if (i < NG * OUTD) g_readout[i] = 0.f;
    if (i < 40) g_bsum[i] = 0;
}

#define WTOT 229376
__global__ void k_conv(const float* __restrict__ W1, const float* __restrict__ F1,
                       const float* __restrict__ W2, const float* __restrict__ W3,
                       const float* __restrict__ x) {
    int idx = blockIdx.x * blockDim.x + threadIdx.x;
    if (idx < WTOT) {
        const float* W; int K, N, base;
        if (idx < 32768)       { W = W1; K = 128; N = 256; base = 0; }
        else if (idx < 65536)  { W = F1; K = 128; N = 256; base = 32768; }
        else if (idx < 196608) { W = W2; K = 512; N = 256; base = 65536; }
        else                   { W = W3; K = 256; N = 128; base = 196608; }
        int li = idx - base;
        int k = li % K, n = li / K;
        g_bh[idx] = __float2half_rn(W[k * N + n]);
    } else {
        int j = idx - WTOT;
        if (j < NP * IND) {
            float v = (j < NN * IND) ? x[j] : 0.f;
            g_xh[j] = __float2half_rn(v);
        }
    }
}

__global__ void k_deg(const int* __restrict__ src, const int* __restrict__ dst) {
    int e = blockIdx.x * blockDim.x + threadIdx.x;
    if (e < NE) {
        atomicAdd(&g_outcnt[src[e]], 1);
        atomicAdd(&g_incnt[dst[e]], 1);
    }
}

// fused scan: per-block scan + single-word atomic publish + parallel lookback
__global__ void k_scan() {
    __shared__ int sh[1024];
    __shared__ int pvals[40];
    __shared__ int pre;
    int b = blockIdx.x, t = threadIdx.x;
    int idx = b * 1024 + t;
    int v = (idx < NN) ? g_incnt[idx] : 0;
    if (idx < NN) {
        g_ininv[idx]  = rsqrtf((float)max(v, 1));
        g_outinv[idx] = rsqrtf((float)max(g_outcnt[idx], 1));
    }
    sh[t] = v;
    __syncthreads();
#pragma unroll
    for (int off = 1; off < 1024; off <<= 1) {
        int u = (t >= off) ? sh[t - off] : 0;
        __syncthreads();
        sh[t] += u;
        __syncthreads();
    }
    int incl = sh[t];
    if (t == 1023) atomicExch(&g_bsum[b], incl | SFLAG);
    if (t < b) {
        int a;
        do { a = atomicAdd(&g_bsum[t], 0); } while (!(a & SFLAG));
        pvals[t] = a & ~SFLAG;
    }
    __syncthreads();
    if (t == 0) {
        int s = 0;
        for (int i = 0; i < b; i++) s += pvals[i];
        pre = s;
    }
    __syncthreads();
    if (idx <= NN) g_rowptr[idx] = incl - v + pre;
}

__global__ void k_place(const int* __restrict__ src, const int* __restrict__ dst,
                        const float* __restrict__ w) {
    int e = blockIdx.x * blockDim.x + threadIdx.x;
    if (e >= NE) return;
    float4 ww = *(const float4*)(w + 4 * e);
    float m = fmaxf(fmaxf(ww.x, ww.y), fmaxf(ww.z, ww.w));
    int d = dst[e];
    int s = src[e];
    int pos = g_rowptr[d] + atomicAdd(&g_cursor[d], 1);
    g_ep[pos] = make_int2(s, __float_as_int(m * g_outinv[s]));
}

// ---------------- aggregation: one warp per dst node, vectorized fp16 gather ----------------
// MODE 1: relu + fp16 out (strided); MODE 2: relu + readout atomics
template <int D, int MODE>
__global__ void k_agg(const __half* __restrict__ in, __half* __restrict__ oh,
                      int ldO, int oOff, const int* __restrict__ gid) {
    constexpr int V = D / 64;  // uint32 (half2) units per lane
    using VT = typename VecSel<V>::T;
    int warp = (blockIdx.x * blockDim.x + threadIdx.x) >> 5;
    int lane = threadIdx.x & 31;
    if (warp >= NP) return;
    if (warp >= NN) {
        if (MODE != 2) {
            VT z = {};
            ((VT*)(oh + (size_t)warp * ldO + oOff))[lane] = z;
        }
        return;
    }
    int beg = g_rowptr[warp];
    int end = g_rowptr[warp + 1];
    float2 acc[V];
#pragma unroll
    for (int v = 0; v < V; v++) acc[v] = make_float2(0.f, 0.f);
    int e = beg;
    for (; e + 3 < end; e += 4) {  // 4-way unroll for MLP
        int2 p0 = g_ep[e], p1 = g_ep[e + 1], p2 = g_ep[e + 2], p3 = g_ep[e + 3];
        VT t0 = ((const VT*)(in + (size_t)p0.x * D))[lane];
        VT t1 = ((const VT*)(in + (size_t)p1.x * D))[lane];
        VT t2 = ((const VT*)(in + (size_t)p2.x * D))[lane];
        VT t3 = ((const VT*)(in + (size_t)p3.x * D))[lane];
        float c0 = __int_as_float(p0.y), c1 = __int_as_float(p1.y);
        float c2 = __int_as_float(p2.y), c3 = __int_as_float(p3.y);
        const uint32_t* w0 = (const uint32_t*)&t0;
        const uint32_t* w1 = (const uint32_t*)&t1;
        const uint32_t* w2 = (const uint32_t*)&t2;
        const uint32_t* w3 = (const uint32_t*)&t3;
#pragma unroll
        for (int v = 0; v < V; v++) {
            float2 f0 = __half22float2(*(const __half2*)&w0[v]);
            float2 f1 = __half22float2(*(const __half2*)&w1[v]);
            float2 f2 = __half22float2(*(const __half2*)&w2[v]);
            float2 f3 = __half22float2(*(const __half2*)&w3[v]);
            acc[v].x = fmaf(c0, f0.x, fmaf(c1, f1.x, fmaf(c2, f2.x, fmaf(c3, f3.x, acc[v].x))));
            acc[v].y = fmaf(c0, f0.y, fmaf(c1, f1.y, fmaf(c2, f2.y, fmaf(c3, f3.y, acc[v].y))));
        }
    }
    for (; e < end; e++) {
        int2 p = g_ep[e];
        float c = __int_as_float(p.y);
        VT t = ((const VT*)(in + (size_t)p.x * D))[lane];
        const uint32_t* w = (const uint32_t*)&t;
#pragma unroll
        for (int v = 0; v < V; v++) {
            float2 f = __half22float2(*(const __half2*)&w[v]);
            acc[v].x = fmaf(c, f.x, acc[v].x);
            acc[v].y = fmaf(c, f.y, acc[v].y);
        }
    }
    float inv = g_ininv[warp];
#pragma unroll
    for (int v = 0; v < V; v++) {
        acc[v].x = fmaxf(acc[v].x * inv, 0.f);
        acc[v].y = fmaxf(acc[v].y * inv, 0.f);
    }
    if (MODE == 2) {
        int g = gid[warp];
        float* r = g_readout + g * OUTD + lane * 4;
        atomicAdd(r + 0, acc[0].x);
        atomicAdd(r + 1, acc[0].y);
        atomicAdd(r + 2, acc[1].x);
        atomicAdd(r + 3, acc[1].y);
    } else {
        VT ov;
        uint32_t* ow = (uint32_t*)&ov;
#pragma unroll
        for (int v = 0; v < V; v++) {
            __half2 a = __floats2half2_rn(acc[v].x, acc[v].y);
            ow[v] = *(uint32_t*)&a;
        }
        ((VT*)(oh + (size_t)warp * ldO + oOff))[lane] = ov;
    }
}

// ---------------- fp16 single-pass mma.sync GEMM, 3-stage pipeline ----------------
// Block tile 128x128 (blockIdx.y = N-block), BK=32/stage, 3 stages. Raw fp16 out.
template <int K>
__global__ __launch_bounds__(256, 2) void k_mma(
    const __half* __restrict__ Ah, const __half* __restrict__ Bh,
    __half* __restrict__ Ch, int ldC, int colOff) {
    extern __shared__ __align__(16) uint8_t smem[];
    constexpr int NC = K / 32;
    constexpr uint32_t AH_ = 0, BH_ = 10240, STG = 20480;
    const int tid = threadIdx.x;
    const int wid = tid >> 5, lane = tid & 31;
    const int wm = wid & 3, wn = wid >> 2;
    const int m0 = blockIdx.x * 128;
    const int nblk = blockIdx.y * 128;
    const uint32_t sb = smem_u32(smem);

    float acc[2][8][4];
#pragma unroll
    for (int mi = 0; mi < 2; mi++)
#pragma unroll
        for (int ni = 0; ni < 8; ni++)
#pragma unroll
            for (int r = 0; r < 4; r++) acc[mi][ni][r] = 0.f;

    const int lrow = tid & 127;
    const bool isB = tid >= 128;
    const __half* gS = isB ? (Bh + (size_t)(nblk + lrow) * K)
                           : (Ah + (size_t)(m0 + lrow) * K);
    const uint32_t gD = (isB ? BH_ : AH_) + (uint32_t)lrow * 80;

    const uint32_t aoff = AH_ + (uint32_t)(wm * 32 + (lane & 7) + ((lane >> 3) & 1) * 8) * 80 +
                          (lane >> 4) * 16;
    const uint32_t boff = BH_ + (uint32_t)(wn * 64 + ((lane >> 4) & 1) * 8 + (lane & 7)) * 80 +
                          ((lane >> 3) & 1) * 16;

    {
        uint32_t st = sb;
        const __half* gp = gS;
#pragma unroll
        for (int j = 0; j < 4; j++) cpa16(st + gD + j * 16, gp + j * 8);
        cpa_commit();
        st = sb + STG;
        gp = gS + 32;
#pragma unroll
        for (int j = 0; j < 4; j++) cpa16(st + gD + j * 16, gp + j * 8);
        cpa_commit();
    }

    for (int c = 0; c < NC; c++) {
        if (c + 1 < NC)
            asm volatile("cp.async.wait_group 1;" ::: "memory");
        else
            asm volatile("cp.async.wait_group 0;" ::: "memory");
        __syncthreads();
        if (c + 2 < NC) {
            uint32_t st = sb + ((c + 2) % 3) * STG;
            const __half* gp = gS + (c + 2) * 32;
#pragma unroll
            for (int j = 0; j < 4; j++) cpa16(st + gD + j * 16, gp + j * 8);
            cpa_commit();
        }
        uint32_t st = sb + (c % 3) * STG;
#pragma unroll
        for (int kk = 0; kk < 2; kk++) {
            const uint32_t ko = kk * 32;
            uint32_t af[2][4], bf[8][2];
#pragma unroll
            for (int mi = 0; mi < 2; mi++) LDSM4(af[mi], st + aoff + mi * 1280 + ko);
#pragma unroll
            for (int p = 0; p < 4; p++) {
                uint32_t r4[4];
                LDSM4(r4, st + boff + p * 1280 + ko);
                bf[2 * p][0] = r4[0]; bf[2 * p][1] = r4[1];
                bf[2 * p + 1][0] = r4[2]; bf[2 * p + 1][1] = r4[3];
            }
#pragma unroll
            for (int mi = 0; mi < 2; mi++)
#pragma unroll
                for (int ni = 0; ni < 8; ni++) MMA16816(acc[mi][ni], af[mi], bf[ni]);
        }
    }

    const int g = lane >> 2, q = lane & 3;
#pragma unroll
    for (int mi = 0; mi < 2; mi++)
#pragma unroll
        for (int ni = 0; ni < 8; ni++) {
            int r0 = m0 + wm * 32 + mi * 16 + g;
            int cc = colOff + nblk + wn * 64 + ni * 8 + 2 * q;
            __half2 a = __floats2half2_rn(acc[mi][ni][0], acc[mi][ni][1]);
            __half2 b = __floats2half2_rn(acc[mi][ni][2], acc[mi][ni][3]);
            *(__half2*)(Ch + (size_t)r0 * ldC + cc) = a;
            *(__half2*)(Ch + (size_t)(r0 + 8) * ldC + cc) = b;
        }
}

// ---------------- LayerNorm + ReLU on fp16 f1h, write fp16 into c cols [256,512) ----------------
__global__ void k_ln(const float* __restrict__ gamma, const float* __restrict__ beta) {
    int warp = (blockIdx.x * blockDim.x + threadIdx.x) >> 5;
    int lane = threadIdx.x & 31;
    if (warp >= NP) return;
    const uint4* row = (const uint4*)(g_f1h + (size_t)warp * H4);
    uint4 u = row[lane];  // 8 halves per lane
    float f[8];
#pragma unroll
    for (int i = 0; i < 4; i++) {
        float2 p = __half22float2(*(const __half2*)(((const uint32_t*)&u) + i));
        f[2 * i] = p.x;
        f[2 * i + 1] = p.y;
    }
    float s = 0.f, ss = 0.f;
#pragma unroll
    for (int i = 0; i < 8; i++) { s += f[i]; ss += f[i] * f[i]; }
#pragma unroll
    for (int o = 16; o > 0; o >>= 1) {
        s += __shfl_xor_sync(0xffffffffu, s, o);
        ss += __shfl_xor_sync(0xffffffffu, ss, o);
    }
    float mean = s * (1.f / 256.f);
    float var = ss * (1.f / 256.f) - mean * mean;
    float rstd = rsqrtf(var + 1e-5f);
    float4 g0 = ((const float4*)gamma)[2 * lane], g1 = ((const float4*)gamma)[2 * lane + 1];
    float4 b0 = ((const float4*)beta)[2 * lane], b1 = ((const float4*)beta)[2 * lane + 1];
    float gv[8] = {g0.x, g0.y, g0.z, g0.w, g1.x, g1.y, g1.z, g1.w};
    float bv[8] = {b0.x, b0.y, b0.z, b0.w, b1.x, b1.y, b1.z, b1.w};
    uint32_t outw[4];
#pragma unroll
    for (int i = 0; i < 4; i++) {
        float v0 = fmaxf((f[2 * i] - mean) * rstd * gv[2 * i] + bv[2 * i], 0.f);
        float v1 = fmaxf((f[2 * i + 1] - mean) * rstd * gv[2 * i + 1] + bv[2 * i + 1], 0.f);
        __half2 h = __floats2half2_rn(v0, v1);
        outw[i] = *(uint32_t*)&h;
    }
    ((uint4*)(g_c + (size_t)warp * CAT + H4))[lane] = *(uint4*)outw;
}

// ---------------- readout normalize ----------------
__global__ void k_norm(float* __restrict__ out) {
    int b = blockIdx.x;
    int t = threadIdx.x;  // 128 threads
    float v = g_readout[b * OUTD + t];
    float ss = v * v;
#pragma unroll
    for (int o = 16; o > 0; o >>= 1) ss += __shfl_xor_sync(0xffffffffu, ss, o);
    __shared__ float sw[4];
    if ((t & 31) == 0) sw[t >> 5] = ss;
    __syncthreads();
    float tot = sw[0] + sw[1] + sw[2] + sw[3];
    float norm = fmaxf(sqrtf(tot), 1e-12f);
    out[b * OUTD + t] = v / norm;
}

// ---------------- launch ----------------
extern "C" void kernel_launch(void* const* d_in, const int* in_sizes, int n_in,
                              void* d_out, int out_size) {
    const float* x    = (const float*)d_in[0];
    const float* w    = (const float*)d_in[1];
    const float* W1   = (const float*)d_in[2];
    const float* fc1W = (const float*)d_in[3];
    const float* gam  = (const float*)d_in[4];
    const float* bet  = (const float*)d_in[5];
    const float* W2   = (const float*)d_in[6];
    const float* W3   = (const float*)d_in[7];
    const int*   src  = (const int*)d_in[8];
    const int*   dst  = (const int*)d_in[9];
    const int*   gid  = (const int*)d_in[10];
    float* out = (float*)d_out;

    __half *p_bh, *p_xh, *p_y1, *p_f1h, *p_c, *p_y2, *p_x2, *p_y3;
    cudaGetSymbolAddress((void**)&p_bh, g_bh);
    cudaGetSymbolAddress((void**)&p_xh, g_xh);
    cudaGetSymbolAddress((void**)&p_y1, g_y1);
    cudaGetSymbolAddress((void**)&p_f1h, g_f1h);
    cudaGetSymbolAddress((void**)&p_c, g_c);
    cudaGetSymbolAddress((void**)&p_y2, g_y2);
    cudaGetSymbolAddress((void**)&p_x2, g_x2);
    cudaGetSymbolAddress((void**)&p_y3, g_y3);

    const int SMEM = 61440;
    cudaFuncSetAttribute(k_mma<128>, cudaFuncAttributeMaxDynamicSharedMemorySize, SMEM);
    cudaFuncSetAttribute(k_mma<512>, cudaFuncAttributeMaxDynamicSharedMemorySize, SMEM);
    cudaFuncSetAttribute(k_mma<256>, cudaFuncAttributeMaxDynamicSharedMemorySize, SMEM);

    // side streams + events (created once, on first — non-capture — call)
    static cudaStream_t s1 = nullptr, s2 = nullptr;
    static cudaEvent_t ev0 = nullptr, ev_conv = nullptr, ev_g1 = nullptr, ev_fc1 = nullptr;
    if (s1 == nullptr) {
        cudaStreamCreateWithFlags(&s1, cudaStreamNonBlocking);
        cudaStreamCreateWithFlags(&s2, cudaStreamNonBlocking);
        cudaEventCreateWithFlags(&ev0, cudaEventDisableTiming);
        cudaEventCreateWithFlags(&ev_conv, cudaEventDisableTiming);
        cudaEventCreateWithFlags(&ev_g1, cudaEventDisableTiming);
        cudaEventCreateWithFlags(&ev_fc1, cudaEventDisableTiming);
    }

    const int TB = 256;
    const int AGG_BLK = (NP * 32 + TB - 1) / TB;
    const int GX = NP / 128;   // 313

    // ---- fork: side stream 1 = conversion + layer-1 GEMM (graph-independent)
    cudaEventRecord(ev0, 0);
    cudaStreamWaitEvent(s1, ev0, 0);
    k_conv<<<(WTOT + NP * IND + TB - 1) / TB, TB, 0, s1>>>(W1, fc1W, W2, W3, x);
    cudaEventRecord(ev_conv, s1);
    k_mma<128><<<dim3(GX, 2), TB, SMEM, s1>>>(p_xh, p_bh + 0, p_y1, H4, 0);
    cudaEventRecord(ev_g1, s1);
    // side stream 2: fc1 GEMM (raw) + LN+relu into concat — forks right after conv
    cudaStreamWaitEvent(s2, ev_conv, 0);
    k_mma<128><<<dim3(GX, 2), TB, SMEM, s2>>>(p_xh, p_bh + 32768, p_f1h, H4, 0);
    k_ln<<<AGG_BLK, TB, 0, s2>>>(gam, bet);
    cudaEventRecord(ev_fc1, s2);

    // main chain: CSR build
    k_zero<<<(NN + TB - 1) / TB, TB>>>();
    k_deg<<<(NE + TB - 1) / TB, TB>>>(src, dst);
    k_scan<<<40, 1024>>>();
    k_place<<<(NE + TB - 1) / TB, TB>>>(src, dst, w);
    // layer 1 aggregation: gather y1 (256-d), relu, write concat cols [0,256)
    cudaStreamWaitEvent(0, ev_g1, 0);
    k_agg<H4, 1><<<AGG_BLK, TB>>>(p_y1, p_c, CAT, 0, nullptr);
    // join fc1, then layer 2: GEMM 512->256, agg + relu
    cudaStreamWaitEvent(0, ev_fc1, 0);
    k_mma<512><<<dim3(GX, 2), TB, SMEM>>>(p_c, p_bh + 65536, p_y2, H4, 0);
    k_agg<H4, 1><<<AGG_BLK, TB>>>(p_y2, p_x2, H4, 0, nullptr);
    // layer 3: GEMM 256->128, agg + relu + readout
    k_mma<256><<<dim3(GX, 1), TB, SMEM>>>(p_x2, p_bh + 196608, p_y3, OUTD, 0);
    k_agg<OUTD, 2><<<AGG_BLK, TB>>>(p_y3, nullptr, 0, 0, gid);
    // final L2 normalize
    k_norm<<<NG, OUTD>>>(out);
}